// round 16
// baseline (speedup 1.0000x reference)
#include <cuda_runtime.h>
#include <cuda_bf16.h>
#include <stdint.h>

#define NMAX 100000
#define EMAX 1000000
#define D 64
#define NSCANMAX 128   // >= ceil(NMAX/1024)

typedef unsigned long long u64;

// ---------------- scratch (device globals; ~35 MB) ----------------
__device__ __align__(16) __nv_bfloat16 g_b0[NMAX * D]; // bf16 dinv*x
__device__ __align__(16) __nv_bfloat16 g_b1[NMAX * D]; // bf16 dinv*x1
__device__ float g_dinv[NMAX];
__device__ int   g_deg [NMAX];        // statically 0; k_scan re-zeroes after reading
__device__ int   g_ptr [NMAX];
__device__ int   g_cur [NMAX];
__device__ int   g_src [2 * EMAX];    // CSR: src node only (weights folded into y)
__device__ int   g_scanstat[NSCANMAX];
__device__ int   g_ticket;
// Static init = 1 (int64 assumed). Only ever cleared (idempotent across replays).
__device__ int   g_is64 = 1;

// ---------------- f32x2 packed helpers ----------------
__device__ __forceinline__ u64 pk2(float a, float b) {
    u64 r; asm("mov.b64 %0, {%1, %2};" : "=l"(r) : "f"(a), "f"(b)); return r;
}
__device__ __forceinline__ u64 fma2(u64 a, u64 b, u64 c) {
    u64 d; asm("fma.rn.f32x2 %0, %1, %2, %3;" : "=l"(d) : "l"(a), "l"(b), "l"(c)); return d;
}
__device__ __forceinline__ u64 add2(u64 a, u64 b) {
    u64 d; asm("add.rn.f32x2 %0, %1, %2;" : "=l"(d) : "l"(a), "l"(b)); return d;
}
__device__ __forceinline__ u64 mul2(u64 a, u64 b) {
    u64 d; asm("mul.rn.f32x2 %0, %1, %2;" : "=l"(d) : "l"(a), "l"(b)); return d;
}
__device__ __forceinline__ float2 up2(u64 a) {
    float2 f; asm("mov.b64 {%0, %1}, %2;" : "=f"(f.x), "=f"(f.y) : "l"(a)); return f;
}
// bf16x2 word -> packed f32x2 (exact): lo = w<<16, hi = w & 0xFFFF0000
__device__ __forceinline__ u64 bf2f2(unsigned w) {
    unsigned lo = w << 16;
    unsigned hi = w & 0xFFFF0000u;
    u64 r; asm("mov.b64 %0, {%1, %2};" : "=l"(r) : "r"(lo), "r"(hi));
    return r;
}

__device__ __forceinline__ int get_idx(const void* ei, int i) {
    if (g_is64) return (int)((const long long*)ei)[i];
    return ((const int*)ei)[i];
}

// Bounded dtype sniff: odd 32-bit words of the first min(256, half) logical entries
// (words < 512: in-bounds under BOTH layouts). int64 high words are 0 for node ids.
__device__ __forceinline__ int detect_is32(const int* __restrict__ w32, int twoE,
                                           int* sh_flag) {
    if (threadIdx.x == 0) *sh_flag = 0;
    __syncthreads();
    int lim = twoE >> 1; if (lim > 256) lim = 256;
    if ((int)threadIdx.x < lim && w32[2 * threadIdx.x + 1] != 0) *sh_flag = 1;
    __syncthreads();
    return *sh_flag;
}

// ---- launch 0 (grid-split): [0,NB) normalize x -> out ; [NB,..) degree count ----
__global__ void k_prepcount(const float* __restrict__ emb, const int* __restrict__ w32,
                            float* __restrict__ out, int N, int twoE, int NB) {
    __shared__ int sh_is32;
    int b = blockIdx.x;
    if (b < NB) {
        int gtid = b * blockDim.x + threadIdx.x;
        int warp = gtid >> 5, lane = gtid & 31;
        if (warp < N) {
            float2 v = ((const float2*)(emb + (size_t)warp * D))[lane];
            float s = v.x * v.x + v.y * v.y;
            #pragma unroll
            for (int o = 16; o; o >>= 1) s += __shfl_xor_sync(0xFFFFFFFFu, s, o);
            float inv = 1.0f / fmaxf(sqrtf(s), 1e-12f);
            ((float2*)(out + (size_t)warp * D))[lane] = make_float2(v.x * inv, v.y * inv);
        }
        if (gtid < NSCANMAX) g_scanstat[gtid] = 0;
        if (gtid == 0) g_ticket = 0;
    } else {
        int is32 = detect_is32(w32, twoE, &sh_is32);
        if (is32 && threadIdx.x == 0) g_is64 = 0;      // publish for k_place
        int i = (b - NB) * blockDim.x + threadIdx.x;   // logical entry index
        if (i < twoE) {
            int u = is32 ? w32[i] : (int)((const long long*)w32)[i];
            if ((unsigned)u < (unsigned)N) atomicAdd(&g_deg[u], 1);
        }
    }
}

// ---- single-pass decoupled-lookback scan of deg; dinv = rsqrt(cnt+1); self-clean ----
__global__ void k_scan(int N) {
    __shared__ int s[1024];
    __shared__ int sh_vbid, sh_run;
    int tid = threadIdx.x;
    if (tid == 0) sh_vbid = atomicAdd(&g_ticket, 1);
    __syncthreads();
    int vbid = sh_vbid;
    int i = vbid * 1024 + tid;

    int v = 0;
    if (i < N) {
        v = g_deg[i];
        g_deg[i] = 0;                                   // ready for next replay
        g_dinv[i] = rsqrtf((float)(v + 1));             // +1 = self loop
    }
    s[tid] = v;
    __syncthreads();
    for (int off = 1; off < 1024; off <<= 1) {
        int t = (tid >= off) ? s[tid - off] : 0;
        __syncthreads();
        s[tid] += t;
        __syncthreads();
    }
    int total = s[1023];
    int ex = s[tid] - v;

    if (tid == 0) {
        if (vbid == 0) {
            atomicExch(&g_scanstat[0], (total << 2) | 2);
            sh_run = 0;
        } else {
            atomicExch(&g_scanstat[vbid], (total << 2) | 1);
            int run = 0, p = vbid - 1;
            while (true) {
                int st = atomicAdd(&g_scanstat[p], 0);
                int f = st & 3;
                if (f == 2) { run += st >> 2; break; }
                if (f == 1) { run += st >> 2; p--; }
            }
            atomicExch(&g_scanstat[vbid], ((run + total) << 2) | 2);
            sh_run = run;
        }
    }
    __syncthreads();
    if (i < N) {
        int p = sh_run + ex;
        g_ptr[i] = p;
        g_cur[i] = p;
    }
}

// ---- launch 2 (grid-split): [0,SB) g_b0 = bf16(dinv*x) ; [SB,..) place edges ----
__global__ void k_place(const void* __restrict__ ei, const float* __restrict__ x,
                        int E, int N, int SB) {
    int b = blockIdx.x;
    if (b < SB) {
        int row  = b * 32 + (threadIdx.x >> 3);
        int lane = threadIdx.x & 7;
        if (row >= N) return;
        float di = g_dinv[row];
        const float4* xr = (const float4*)(x + (size_t)row * D + lane * 8);
        float4 v0 = xr[0], v1 = xr[1];
        __nv_bfloat162 o0 = __floats2bfloat162_rn(di * v0.x, di * v0.y);
        __nv_bfloat162 o1 = __floats2bfloat162_rn(di * v0.z, di * v0.w);
        __nv_bfloat162 o2 = __floats2bfloat162_rn(di * v1.x, di * v1.y);
        __nv_bfloat162 o3 = __floats2bfloat162_rn(di * v1.z, di * v1.w);
        *(uint4*)(g_b0 + (size_t)row * D + lane * 8) =
            make_uint4(*(unsigned*)&o0, *(unsigned*)&o1, *(unsigned*)&o2, *(unsigned*)&o3);
    } else {
        int e = (b - SB) * 256 + threadIdx.x;
        if (e >= E) return;
        int u = get_idx(ei, e);
        int v = get_idx(ei, E + e);
        if ((unsigned)u >= (unsigned)N || (unsigned)v >= (unsigned)N) return;
        int p = atomicAdd(&g_cur[v], 1);
        if ((unsigned)p < 2u * EMAX) g_src[p] = u;
        int q = atomicAdd(&g_cur[u], 1);
        if ((unsigned)q < 2u * EMAX) g_src[q] = v;
    }
}

// ---- gather one node's aggregated row into smem (bf16 in, f32x2 acc, L2-only loads) ----
__device__ __forceinline__ void gather_node(const __nv_bfloat16* __restrict__ in,
                                            float* __restrict__ srow,
                                            int node, int lane) {
    uint4 sv = __ldcg((const uint4*)(in + (size_t)node * D) + lane);   // y[v] (self)
    u64 a0 = bf2f2(sv.x), a1 = bf2f2(sv.y), a2 = bf2f2(sv.z), a3 = bf2f2(sv.w);
    int s0  = g_ptr[node];
    int cnt = g_cur[node] - s0;
    int t = 0;
    for (; t + 4 <= cnt; t += 4) {
        int s[4];
        #pragma unroll
        for (int j = 0; j < 4; j++) s[j] = g_src[s0 + t + j];
        uint4 h[4];
        #pragma unroll
        for (int j = 0; j < 4; j++)
            h[j] = __ldcg((const uint4*)(in + (size_t)s[j] * D) + lane);
        #pragma unroll
        for (int j = 0; j < 4; j++) {
            a0 = add2(a0, bf2f2(h[j].x));
            a1 = add2(a1, bf2f2(h[j].y));
            a2 = add2(a2, bf2f2(h[j].z));
            a3 = add2(a3, bf2f2(h[j].w));
        }
    }
    for (; t < cnt; t++) {
        int ss = g_src[s0 + t];
        uint4 h = __ldcg((const uint4*)(in + (size_t)ss * D) + lane);
        a0 = add2(a0, bf2f2(h.x));
        a1 = add2(a1, bf2f2(h.y));
        a2 = add2(a2, bf2f2(h.z));
        a3 = add2(a3, bf2f2(h.w));
    }
    float di = g_dinv[node];
    u64 dd = pk2(di, di);
    a0 = mul2(a0, dd); a1 = mul2(a1, dd);
    a2 = mul2(a2, dd); a3 = mul2(a3, dd);
    float2 f;
    f = up2(a0); srow[0] = f.x; srow[1] = f.y;
    f = up2(a1); srow[2] = f.x; srow[3] = f.y;
    f = up2(a2); srow[4] = f.x; srow[5] = f.y;
    f = up2(a3); srow[6] = f.x; srow[7] = f.y;
}

// ---- gather a 64-node tile into smem with dynamic slot stealing ----
// 32 eight-lane groups pop slots from a shared counter (balances degree skew).
// Caller provides the counter word (any smem int not otherwise used during gather).
__device__ __forceinline__ void gather_tile(const __nv_bfloat16* __restrict__ in,
                                            float* __restrict__ s_in,
                                            int base, int N, int* sh_next) {
    int tid   = threadIdx.x;
    int lane  = tid & 7;
    int gbase = tid & 24;                 // group's first lane within the warp
    unsigned gmask = 0xFFu << gbase;
    if (tid == 0) *sh_next = 32;
    __syncthreads();

    int slot = tid >> 3;                  // initial static slots 0..31
    while (slot < 64) {
        int node = base + slot;
        float* srow = s_in + slot * 64 + lane * 8;
        if (node < N) {
            gather_node(in, srow, node, lane);
        } else {
            #pragma unroll
            for (int i = 0; i < 8; i++) srow[i] = 0.f;
        }
        int nxt = 0;
        if (lane == 0) nxt = atomicAdd(sh_next, 1);
        slot = __shfl_sync(gmask, nxt, gbase);
    }
}

// ---- fused layer 1: a = Agg(y0); x1 = leaky(a W1^T + b1); out += x1; g_b1 = bf16(dinv*x1) ----
__global__ void k_gg1(const float* __restrict__ W, const float* __restrict__ b,
                      float* __restrict__ out, int N) {
    __shared__ __align__(16) float s_in[64 * 64];
    __shared__ __align__(16) float s_wt[64 * 64];  // s_wt[k*64+j] = W[j*64+k]
    __shared__ int sh_next;                        // 32KB + 4B: fits

    int tid  = threadIdx.x;
    int base = blockIdx.x * 64;

    #pragma unroll
    for (int r = 0; r < 16; r++) {
        int idx = tid + 256 * r;
        s_wt[(idx >> 6) * 64 + (idx & 63)] = W[(idx & 63) * 64 + (idx >> 6)];
    }
    gather_tile(g_b0, s_in, base, N, &sh_next);
    __syncthreads();

    int ng = tid >> 4, cg = tid & 15;
    int r0 = ng * 4;
    u64 acc[4][2] = {{0,0},{0,0},{0,0},{0,0}};
    const ulonglong2* wt2 = (const ulonglong2*)s_wt;
    #pragma unroll
    for (int k = 0; k < 64; k++) {
        ulonglong2 wv = wt2[k * 16 + cg];
        #pragma unroll
        for (int r = 0; r < 4; r++) {
            float x = s_in[(r0 + r) * 64 + k];
            u64 xx = pk2(x, x);
            acc[r][0] = fma2(xx, wv.x, acc[r][0]);
            acc[r][1] = fma2(xx, wv.y, acc[r][1]);
        }
    }

    float4 bb = ((const float4*)b)[cg];
    #pragma unroll
    for (int r = 0; r < 4; r++) {
        int row = base + r0 + r;
        if (row >= N) break;
        float2 c01 = up2(acc[r][0]);
        float2 c23 = up2(acc[r][1]);
        float4 v = make_float4(c01.x + bb.x, c01.y + bb.y, c23.x + bb.z, c23.y + bb.w);
        v.x = v.x > 0.f ? v.x : 0.01f*v.x; v.y = v.y > 0.f ? v.y : 0.01f*v.y;
        v.z = v.z > 0.f ? v.z : 0.01f*v.z; v.w = v.w > 0.f ? v.w : 0.01f*v.w;
        float di = g_dinv[row];
        __nv_bfloat162* bo = (__nv_bfloat162*)(g_b1 + (size_t)row * D + cg * 4);
        bo[0] = __floats2bfloat162_rn(di * v.x, di * v.y);
        bo[1] = __floats2bfloat162_rn(di * v.z, di * v.w);
        size_t o = (size_t)row * 16 + cg;
        float4 ov = ((const float4*)out)[o];     // holds x
        ov.x += v.x; ov.y += v.y; ov.z += v.z; ov.w += v.w;
        ((float4*)out)[o] = ov;
    }
}

// ---- fused layers 2+3: a = Agg(y1); out += leaky(a W2^T + b2) + (a W3^T + b3) ----
// smem is exactly 48KB: the work-steal counter borrows s_w2[0] during the gather
// phase; the real W2[0] value is patched in afterwards (before the GEMM).
__global__ void k_gg23(const float* __restrict__ W2, const float* __restrict__ b2,
                       const float* __restrict__ W3, const float* __restrict__ b3,
                       float* __restrict__ out, int N) {
    __shared__ __align__(16) float s_in[64 * 64];
    __shared__ __align__(16) float s_w2[64 * 64];
    __shared__ __align__(16) float s_w3[64 * 64];

    int tid  = threadIdx.x;
    int base = blockIdx.x * 64;

    #pragma unroll
    for (int r = 0; r < 16; r++) {
        int idx = tid + 256 * r;
        int j = idx & 63, k = idx >> 6;
        if (idx != 0) s_w2[k * 64 + j] = W2[j * 64 + k];  // skip s_w2[0] (counter)
        s_w3[k * 64 + j] = W3[j * 64 + k];
    }
    gather_tile(g_b1, s_in, base, N, (int*)s_w2);
    __syncthreads();                                      // all pops done
    if (tid == 0) s_w2[0] = W2[0];                        // patch real weight (k=0,j=0)
    __syncthreads();

    int ng = tid >> 4, cg = tid & 15;
    int r0 = ng * 4;
    u64 p[4][2] = {{0,0},{0,0},{0,0},{0,0}};
    u64 q[4][2] = {{0,0},{0,0},{0,0},{0,0}};
    const ulonglong2* w22 = (const ulonglong2*)s_w2;
    const ulonglong2* w32 = (const ulonglong2*)s_w3;
    #pragma unroll
    for (int k = 0; k < 64; k++) {
        ulonglong2 u2 = w22[k * 16 + cg];
        ulonglong2 v2 = w32[k * 16 + cg];
        #pragma unroll
        for (int r = 0; r < 4; r++) {
            float x = s_in[(r0 + r) * 64 + k];
            u64 xx = pk2(x, x);
            p[r][0] = fma2(xx, u2.x, p[r][0]);
            p[r][1] = fma2(xx, u2.y, p[r][1]);
            q[r][0] = fma2(xx, v2.x, q[r][0]);
            q[r][1] = fma2(xx, v2.y, q[r][1]);
        }
    }

    float4 bb2 = ((const float4*)b2)[cg];
    float4 bb3 = ((const float4*)b3)[cg];
    #pragma unroll
    for (int r = 0; r < 4; r++) {
        int row = base + r0 + r;
        if (row >= N) break;
        float2 p01 = up2(p[r][0]), p23 = up2(p[r][1]);
        float2 q01 = up2(q[r][0]), q23 = up2(q[r][1]);
        float4 pv = make_float4(p01.x + bb2.x, p01.y + bb2.y, p23.x + bb2.z, p23.y + bb2.w);
        pv.x = pv.x > 0.f ? pv.x : 0.01f*pv.x; pv.y = pv.y > 0.f ? pv.y : 0.01f*pv.y;
        pv.z = pv.z > 0.f ? pv.z : 0.01f*pv.z; pv.w = pv.w > 0.f ? pv.w : 0.01f*pv.w;
        float4 qv = make_float4(q01.x + bb3.x, q01.y + bb3.y, q23.x + bb3.z, q23.y + bb3.w);
        size_t o = (size_t)row * 16 + cg;
        float4 ov = ((const float4*)out)[o];     // holds x + x1
        ov.x += pv.x + qv.x;
        ov.y += pv.y + qv.y;
        ov.z += pv.z + qv.z;
        ov.w += pv.w + qv.w;
        ((float4*)out)[o] = ov;
    }
}

// ---------------- launch ----------------
extern "C" void kernel_launch(void* const* d_in, const int* in_sizes, int n_in,
                              void* d_out, int out_size) {
    const void*  ei  = d_in[0];
    const float* emb = (const float*)d_in[1];
    const float* W1 = (const float*)d_in[2];
    const float* b1 = (const float*)d_in[3];
    const float* W2 = (const float*)d_in[4];
    const float* b2 = (const float*)d_in[5];
    const float* W3 = (const float*)d_in[6];
    const float* b3 = (const float*)d_in[7];
    float* out = (float*)d_out;

    int E = in_sizes[0] / 2;
    int N = in_sizes[1] / D;

    int NB = (N * 32 + 255) / 256;                // normalize blocks (warp/node)
    int CB = (2 * E + 255) / 256;                 // count blocks
    k_prepcount<<<NB + CB, 256>>>(emb, (const int*)ei, out, N, 2 * E, NB);

    int B = (N + 1023) / 1024;
    k_scan<<<B, 1024>>>(N);

    int SB = (N + 31) / 32;                       // scale blocks (32 rows / block)
    int PB = (E + 255) / 256;                     // place blocks
    k_place<<<SB + PB, 256>>>(ei, out, E, N, SB);

    int gb = (N + 63) / 64;                       // fused gather+gemm blocks
    k_gg1 <<<gb, 256>>>(W1, b1, out, N);
    k_gg23<<<gb, 256>>>(W2, b2, W3, b3, out, N);
}

// round 17
// speedup vs baseline: 1.0157x; 1.0157x over previous
#include <cuda_runtime.h>
#include <cuda_bf16.h>
#include <stdint.h>

#define NMAX 100000
#define EMAX 1000000
#define D 64
#define NSCANMAX 128   // >= ceil(NMAX/1024)

typedef unsigned long long u64;

// ---------------- scratch (device globals; ~35 MB) ----------------
__device__ __align__(16) __nv_bfloat16 g_b0[NMAX * D]; // bf16 dinv*x
__device__ __align__(16) __nv_bfloat16 g_b1[NMAX * D]; // bf16 dinv*x1
__device__ float g_dinv[NMAX];
__device__ int   g_deg [NMAX];        // statically 0; k_scan re-zeroes after reading
__device__ int   g_ptr [NMAX];
__device__ int   g_cur [NMAX];
__device__ int   g_src [2 * EMAX];    // CSR: src node only (weights folded into y)
__device__ int   g_scanstat[NSCANMAX];
__device__ int   g_ticket;
// Static init = 1 (int64 assumed). Only ever cleared (idempotent across replays).
__device__ int   g_is64 = 1;

// ---------------- f32x2 packed helpers ----------------
__device__ __forceinline__ u64 pk2(float a, float b) {
    u64 r; asm("mov.b64 %0, {%1, %2};" : "=l"(r) : "f"(a), "f"(b)); return r;
}
__device__ __forceinline__ u64 fma2(u64 a, u64 b, u64 c) {
    u64 d; asm("fma.rn.f32x2 %0, %1, %2, %3;" : "=l"(d) : "l"(a), "l"(b), "l"(c)); return d;
}
__device__ __forceinline__ u64 add2(u64 a, u64 b) {
    u64 d; asm("add.rn.f32x2 %0, %1, %2;" : "=l"(d) : "l"(a), "l"(b)); return d;
}
__device__ __forceinline__ u64 mul2(u64 a, u64 b) {
    u64 d; asm("mul.rn.f32x2 %0, %1, %2;" : "=l"(d) : "l"(a), "l"(b)); return d;
}
__device__ __forceinline__ float2 up2(u64 a) {
    float2 f; asm("mov.b64 {%0, %1}, %2;" : "=f"(f.x), "=f"(f.y) : "l"(a)); return f;
}
// bf16x2 word -> packed f32x2 (exact): lo = w<<16, hi = w & 0xFFFF0000
__device__ __forceinline__ u64 bf2f2(unsigned w) {
    unsigned lo = w << 16;
    unsigned hi = w & 0xFFFF0000u;
    u64 r; asm("mov.b64 %0, {%1, %2};" : "=l"(r) : "r"(lo), "r"(hi));
    return r;
}

__device__ __forceinline__ int get_idx(const void* ei, int i) {
    if (g_is64) return (int)((const long long*)ei)[i];
    return ((const int*)ei)[i];
}

// Bounded dtype sniff: odd 32-bit words of the first min(256, half) logical entries
// (words < 512: in-bounds under BOTH layouts). int64 high words are 0 for node ids.
__device__ __forceinline__ int detect_is32(const int* __restrict__ w32, int twoE,
                                           int* sh_flag) {
    if (threadIdx.x == 0) *sh_flag = 0;
    __syncthreads();
    int lim = twoE >> 1; if (lim > 256) lim = 256;
    if ((int)threadIdx.x < lim && w32[2 * threadIdx.x + 1] != 0) *sh_flag = 1;
    __syncthreads();
    return *sh_flag;
}

// ---- launch 0 (grid-split): [0,NB) normalize x -> out ; [NB,..) degree count ----
__global__ void k_prepcount(const float* __restrict__ emb, const int* __restrict__ w32,
                            float* __restrict__ out, int N, int twoE, int NB) {
    __shared__ int sh_is32;
    int b = blockIdx.x;
    if (b < NB) {
        int gtid = b * blockDim.x + threadIdx.x;
        int warp = gtid >> 5, lane = gtid & 31;
        if (warp < N) {
            float2 v = ((const float2*)(emb + (size_t)warp * D))[lane];
            float s = v.x * v.x + v.y * v.y;
            #pragma unroll
            for (int o = 16; o; o >>= 1) s += __shfl_xor_sync(0xFFFFFFFFu, s, o);
            float inv = 1.0f / fmaxf(sqrtf(s), 1e-12f);
            ((float2*)(out + (size_t)warp * D))[lane] = make_float2(v.x * inv, v.y * inv);
        }
        if (gtid < NSCANMAX) g_scanstat[gtid] = 0;
        if (gtid == 0) g_ticket = 0;
    } else {
        int is32 = detect_is32(w32, twoE, &sh_is32);
        if (is32 && threadIdx.x == 0) g_is64 = 0;      // publish for k_place
        int i = (b - NB) * blockDim.x + threadIdx.x;   // logical entry index
        if (i < twoE) {
            int u = is32 ? w32[i] : (int)((const long long*)w32)[i];
            if ((unsigned)u < (unsigned)N) atomicAdd(&g_deg[u], 1);
        }
    }
}

// ---- single-pass decoupled-lookback scan of deg; dinv = rsqrt(cnt+1); self-clean ----
__global__ void k_scan(int N) {
    __shared__ int s[1024];
    __shared__ int sh_vbid, sh_run;
    int tid = threadIdx.x;
    if (tid == 0) sh_vbid = atomicAdd(&g_ticket, 1);
    __syncthreads();
    int vbid = sh_vbid;
    int i = vbid * 1024 + tid;

    int v = 0;
    if (i < N) {
        v = g_deg[i];
        g_deg[i] = 0;                                   // ready for next replay
        g_dinv[i] = rsqrtf((float)(v + 1));             // +1 = self loop
    }
    s[tid] = v;
    __syncthreads();
    for (int off = 1; off < 1024; off <<= 1) {
        int t = (tid >= off) ? s[tid - off] : 0;
        __syncthreads();
        s[tid] += t;
        __syncthreads();
    }
    int total = s[1023];
    int ex = s[tid] - v;

    if (tid == 0) {
        if (vbid == 0) {
            atomicExch(&g_scanstat[0], (total << 2) | 2);
            sh_run = 0;
        } else {
            atomicExch(&g_scanstat[vbid], (total << 2) | 1);
            int run = 0, p = vbid - 1;
            while (true) {
                int st = atomicAdd(&g_scanstat[p], 0);
                int f = st & 3;
                if (f == 2) { run += st >> 2; break; }
                if (f == 1) { run += st >> 2; p--; }
            }
            atomicExch(&g_scanstat[vbid], ((run + total) << 2) | 2);
            sh_run = run;
        }
    }
    __syncthreads();
    if (i < N) {
        int p = sh_run + ex;
        g_ptr[i] = p;
        g_cur[i] = p;
    }
}

// ---- launch 2 (grid-split): [0,SB) g_b0 = bf16(dinv*x) ; [SB,..) place edges ----
__global__ void k_place(const void* __restrict__ ei, const float* __restrict__ x,
                        int E, int N, int SB) {
    int b = blockIdx.x;
    if (b < SB) {
        int row  = b * 32 + (threadIdx.x >> 3);
        int lane = threadIdx.x & 7;
        if (row >= N) return;
        float di = g_dinv[row];
        const float4* xr = (const float4*)(x + (size_t)row * D + lane * 8);
        float4 v0 = xr[0], v1 = xr[1];
        __nv_bfloat162 o0 = __floats2bfloat162_rn(di * v0.x, di * v0.y);
        __nv_bfloat162 o1 = __floats2bfloat162_rn(di * v0.z, di * v0.w);
        __nv_bfloat162 o2 = __floats2bfloat162_rn(di * v1.x, di * v1.y);
        __nv_bfloat162 o3 = __floats2bfloat162_rn(di * v1.z, di * v1.w);
        *(uint4*)(g_b0 + (size_t)row * D + lane * 8) =
            make_uint4(*(unsigned*)&o0, *(unsigned*)&o1, *(unsigned*)&o2, *(unsigned*)&o3);
    } else {
        int e = (b - SB) * 256 + threadIdx.x;
        if (e >= E) return;
        int u = get_idx(ei, e);
        int v = get_idx(ei, E + e);
        if ((unsigned)u >= (unsigned)N || (unsigned)v >= (unsigned)N) return;
        int p = atomicAdd(&g_cur[v], 1);
        if ((unsigned)p < 2u * EMAX) g_src[p] = u;
        int q = atomicAdd(&g_cur[u], 1);
        if ((unsigned)q < 2u * EMAX) g_src[q] = v;
    }
}

// ---- gather one node's aggregated row into smem (bf16 in, f32x2 acc, L2-only loads) ----
__device__ __forceinline__ void gather_node(const __nv_bfloat16* __restrict__ in,
                                            float* __restrict__ srow,
                                            int node, int lane) {
    uint4 sv = __ldcg((const uint4*)(in + (size_t)node * D) + lane);   // y[v] (self)
    u64 a0 = bf2f2(sv.x), a1 = bf2f2(sv.y), a2 = bf2f2(sv.z), a3 = bf2f2(sv.w);
    int s0  = g_ptr[node];
    int cnt = g_cur[node] - s0;
    int t = 0;
    for (; t + 4 <= cnt; t += 4) {
        int s[4];
        #pragma unroll
        for (int j = 0; j < 4; j++) s[j] = g_src[s0 + t + j];
        uint4 h[4];
        #pragma unroll
        for (int j = 0; j < 4; j++)
            h[j] = __ldcg((const uint4*)(in + (size_t)s[j] * D) + lane);
        #pragma unroll
        for (int j = 0; j < 4; j++) {
            a0 = add2(a0, bf2f2(h[j].x));
            a1 = add2(a1, bf2f2(h[j].y));
            a2 = add2(a2, bf2f2(h[j].z));
            a3 = add2(a3, bf2f2(h[j].w));
        }
    }
    for (; t < cnt; t++) {
        int ss = g_src[s0 + t];
        uint4 h = __ldcg((const uint4*)(in + (size_t)ss * D) + lane);
        a0 = add2(a0, bf2f2(h.x));
        a1 = add2(a1, bf2f2(h.y));
        a2 = add2(a2, bf2f2(h.z));
        a3 = add2(a3, bf2f2(h.w));
    }
    float di = g_dinv[node];
    u64 dd = pk2(di, di);
    a0 = mul2(a0, dd); a1 = mul2(a1, dd);
    a2 = mul2(a2, dd); a3 = mul2(a3, dd);
    float2 f;
    f = up2(a0); srow[0] = f.x; srow[1] = f.y;
    f = up2(a1); srow[2] = f.x; srow[3] = f.y;
    f = up2(a2); srow[4] = f.x; srow[5] = f.y;
    f = up2(a3); srow[6] = f.x; srow[7] = f.y;
}

// ---- gather a 64-node tile into smem (static 2 batches of 32 slots) ----
__device__ __forceinline__ void gather_tile(const __nv_bfloat16* __restrict__ in,
                                            float* __restrict__ s_in,
                                            int base, int N) {
    int tid  = threadIdx.x;
    int lane = tid & 7;
    #pragma unroll
    for (int bat = 0; bat < 2; bat++) {
        int slot = bat * 32 + (tid >> 3);
        int node = base + slot;
        float* srow = s_in + slot * 64 + lane * 8;
        if (node < N) {
            gather_node(in, srow, node, lane);
        } else {
            #pragma unroll
            for (int i = 0; i < 8; i++) srow[i] = 0.f;
        }
    }
}

// ---- fused layer 1: a = Agg(y0); x1 = leaky(a W1^T + b1); out += x1; g_b1 = bf16(dinv*x1) ----
__global__ void __launch_bounds__(256, 4)
k_gg1(const float* __restrict__ W, const float* __restrict__ b,
      float* __restrict__ out, int N) {
    __shared__ __align__(16) float s_in[64 * 64];
    __shared__ __align__(16) float s_wt[64 * 64];  // s_wt[k*64+j] = W[j*64+k]

    int tid  = threadIdx.x;
    int base = blockIdx.x * 64;

    #pragma unroll
    for (int r = 0; r < 16; r++) {
        int idx = tid + 256 * r;
        s_wt[(idx >> 6) * 64 + (idx & 63)] = W[(idx & 63) * 64 + (idx >> 6)];
    }
    gather_tile(g_b0, s_in, base, N);
    __syncthreads();

    int ng = tid >> 4, cg = tid & 15;
    int r0 = ng * 4;
    u64 acc[4][2] = {{0,0},{0,0},{0,0},{0,0}};
    const ulonglong2* wt2 = (const ulonglong2*)s_wt;
    const float4* s_in4 = (const float4*)s_in;
    #pragma unroll
    for (int k4 = 0; k4 < 16; k4++) {              // k = 4*k4 .. 4*k4+3
        float4 xv[4];
        #pragma unroll
        for (int r = 0; r < 4; r++) xv[r] = s_in4[(r0 + r) * 16 + k4];  // broadcast LDS.128
        #pragma unroll
        for (int kk = 0; kk < 4; kk++) {
            ulonglong2 wv = wt2[(k4 * 4 + kk) * 16 + cg];
            #pragma unroll
            for (int r = 0; r < 4; r++) {
                float x = ((const float*)&xv[r])[kk];
                u64 xx = pk2(x, x);
                acc[r][0] = fma2(xx, wv.x, acc[r][0]);
                acc[r][1] = fma2(xx, wv.y, acc[r][1]);
            }
        }
    }

    float4 bb = ((const float4*)b)[cg];
    #pragma unroll
    for (int r = 0; r < 4; r++) {
        int row = base + r0 + r;
        if (row >= N) break;
        float2 c01 = up2(acc[r][0]);
        float2 c23 = up2(acc[r][1]);
        float4 v = make_float4(c01.x + bb.x, c01.y + bb.y, c23.x + bb.z, c23.y + bb.w);
        v.x = v.x > 0.f ? v.x : 0.01f*v.x; v.y = v.y > 0.f ? v.y : 0.01f*v.y;
        v.z = v.z > 0.f ? v.z : 0.01f*v.z; v.w = v.w > 0.f ? v.w : 0.01f*v.w;
        float di = g_dinv[row];
        __nv_bfloat162* bo = (__nv_bfloat162*)(g_b1 + (size_t)row * D + cg * 4);
        bo[0] = __floats2bfloat162_rn(di * v.x, di * v.y);
        bo[1] = __floats2bfloat162_rn(di * v.z, di * v.w);
        size_t o = (size_t)row * 16 + cg;
        float4 ov = ((const float4*)out)[o];     // holds x
        ov.x += v.x; ov.y += v.y; ov.z += v.z; ov.w += v.w;
        ((float4*)out)[o] = ov;
    }
}

// ---- fused layers 2+3: a = Agg(y1); out += leaky(a W2^T + b2) + (a W3^T + b3) ----
__global__ void __launch_bounds__(256, 4)
k_gg23(const float* __restrict__ W2, const float* __restrict__ b2,
       const float* __restrict__ W3, const float* __restrict__ b3,
       float* __restrict__ out, int N) {
    __shared__ __align__(16) float s_in[64 * 64];
    __shared__ __align__(16) float s_w2[64 * 64];
    __shared__ __align__(16) float s_w3[64 * 64];   // exactly 48KB total

    int tid  = threadIdx.x;
    int base = blockIdx.x * 64;

    #pragma unroll
    for (int r = 0; r < 16; r++) {
        int idx = tid + 256 * r;
        int j = idx & 63, k = idx >> 6;
        s_w2[k * 64 + j] = W2[j * 64 + k];
        s_w3[k * 64 + j] = W3[j * 64 + k];
    }
    gather_tile(g_b1, s_in, base, N);
    __syncthreads();

    int ng = tid >> 4, cg = tid & 15;
    int r0 = ng * 4;
    u64 p[4][2] = {{0,0},{0,0},{0,0},{0,0}};
    u64 q[4][2] = {{0,0},{0,0},{0,0},{0,0}};
    const ulonglong2* w22 = (const ulonglong2*)s_w2;
    const ulonglong2* w32 = (const ulonglong2*)s_w3;
    const float4* s_in4 = (const float4*)s_in;
    #pragma unroll
    for (int k4 = 0; k4 < 16; k4++) {
        float4 xv[4];
        #pragma unroll
        for (int r = 0; r < 4; r++) xv[r] = s_in4[(r0 + r) * 16 + k4];  // broadcast LDS.128
        #pragma unroll
        for (int kk = 0; kk < 4; kk++) {
            int k = k4 * 4 + kk;
            ulonglong2 u2 = w22[k * 16 + cg];
            ulonglong2 v2 = w32[k * 16 + cg];
            #pragma unroll
            for (int r = 0; r < 4; r++) {
                float x = ((const float*)&xv[r])[kk];
                u64 xx = pk2(x, x);
                p[r][0] = fma2(xx, u2.x, p[r][0]);
                p[r][1] = fma2(xx, u2.y, p[r][1]);
                q[r][0] = fma2(xx, v2.x, q[r][0]);
                q[r][1] = fma2(xx, v2.y, q[r][1]);
            }
        }
    }

    float4 bb2 = ((const float4*)b2)[cg];
    float4 bb3 = ((const float4*)b3)[cg];
    #pragma unroll
    for (int r = 0; r < 4; r++) {
        int row = base + r0 + r;
        if (row >= N) break;
        float2 p01 = up2(p[r][0]), p23 = up2(p[r][1]);
        float2 q01 = up2(q[r][0]), q23 = up2(q[r][1]);
        float4 pv = make_float4(p01.x + bb2.x, p01.y + bb2.y, p23.x + bb2.z, p23.y + bb2.w);
        pv.x = pv.x > 0.f ? pv.x : 0.01f*pv.x; pv.y = pv.y > 0.f ? pv.y : 0.01f*pv.y;
        pv.z = pv.z > 0.f ? pv.z : 0.01f*pv.z; pv.w = pv.w > 0.f ? pv.w : 0.01f*pv.w;
        float4 qv = make_float4(q01.x + bb3.x, q01.y + bb3.y, q23.x + bb3.z, q23.y + bb3.w);
        size_t o = (size_t)row * 16 + cg;
        float4 ov = ((const float4*)out)[o];     // holds x + x1
        ov.x += pv.x + qv.x;
        ov.y += pv.y + qv.y;
        ov.z += pv.z + qv.z;
        ov.w += pv.w + qv.w;
        ((float4*)out)[o] = ov;
    }
}

// ---------------- launch ----------------
extern "C" void kernel_launch(void* const* d_in, const int* in_sizes, int n_in,
                              void* d_out, int out_size) {
    const void*  ei  = d_in[0];
    const float* emb = (const float*)d_in[1];
    const float* W1 = (const float*)d_in[2];
    const float* b1 = (const float*)d_in[3];
    const float* W2 = (const float*)d_in[4];
    const float* b2 = (const float*)d_in[5];
    const float* W3 = (const float*)d_in[6];
    const float* b3 = (const float*)d_in[7];
    float* out = (float*)d_out;

    int E = in_sizes[0] / 2;
    int N = in_sizes[1] / D;

    int NB = (N * 32 + 255) / 256;                // normalize blocks (warp/node)
    int CB = (2 * E + 255) / 256;                 // count blocks
    k_prepcount<<<NB + CB, 256>>>(emb, (const int*)ei, out, N, 2 * E, NB);

    int B = (N + 1023) / 1024;
    k_scan<<<B, 1024>>>(N);

    int SB = (N + 31) / 32;                       // scale blocks (32 rows / block)
    int PB = (E + 255) / 256;                     // place blocks
    k_place<<<SB + PB, 256>>>(ei, out, E, N, SB);

    int gb = (N + 63) / 64;                       // fused gather+gemm blocks
    k_gg1 <<<gb, 256>>>(W1, b1, out, N);
    k_gg23<<<gb, 256>>>(W2, b2, W3, b3, out, N);
}